// round 3
// baseline (speedup 1.0000x reference)
#include <cuda_runtime.h>
#include <math.h>
#include <float.h>

#define Bn   4
#define Hn   32
#define HKV  8
#define Gn   4
#define Dn   128
#define Pn   128
#define Sn   64
#define KP   16
#define NEGV (-1000000000.0f)
#define SM_SCALE 0.08838834764831845f

// Scratch (allocation-free rule: __device__ globals)
__device__ float g_scores[Bn*Hn*Pn*Sn];   // 4 MB masked score matrix
__device__ float g_stats [Bn*Hn*Pn];      // per-page max
__device__ int   g_sel   [Bn*Hn*KP];
__device__ float g_cur   [Bn*Hn];         // current-token score
__device__ float g_max   [Bn*Hn];         // softmax max per head
__device__ float g_part  [Bn*Hn*KP*Dn];   // per-(head,page) partial sum(exp*V)
__device__ float g_pden  [Bn*Hn*KP];      // per-(head,page) partial denom
__device__ int   g_cnt   [Bn*Hn];         // arrival counters (zero-init)

__device__ __forceinline__ void rope_cs(int t, float pos, float& c, float& s) {
    float inv = 1.0f / powf(10000.0f, (float)t * (2.0f / (float)Dn));
    float ang = pos * inv;
    c = cosf(ang); s = sinf(ang);
}

// ---------------------------------------------------------------- kernel 1
// One block per (page, b*HKV). 128 threads: 2 per token (D halves).
// Inline q-RoPE (pre-scaled), 16-deep int4 K loads, scores + page stats.
__global__ void __launch_bounds__(128, 5)
score_kernel(const float* __restrict__ q,
             const int*   __restrict__ k_cache,
             const float* __restrict__ kv_scale,
             const int*   __restrict__ lengths,
             const int*   __restrict__ timestep)
{
    int p   = blockIdx.x;
    int bh  = blockIdx.y;            // b*HKV + hkv
    int b   = bh >> 3, hkv = bh & 7;
    int tid = threadIdx.x;           // 128
    int len = max(lengths[b], 1);
    int head0 = b*Hn + hkv*Gn;

    if (p*Sn >= len) {
        // fully masked page. Only page Pn-1 can ever be selected while masked.
        if (p == Pn-1 && tid < Sn) {
            #pragma unroll
            for (int g = 0; g < Gn; g++)
                g_scores[(size_t)(head0+g)*Pn*Sn + p*Sn + tid] = NEGV;
        }
        if (tid < Gn) g_stats[(head0+tid)*Pn + p] = NEGV;
        return;
    }

    __shared__ float4 qs4[Gn][Dn/4];
    {
        float pos = (float)(timestep[0] - 1);
        float sk_scale = kv_scale[0] * SM_SCALE;
        float* qf = (float*)qs4;
        #pragma unroll
        for (int idx = tid; idx < Gn*64; idx += 128) {
            int g = idx >> 6, t = idx & 63;
            float c, s; rope_cs(t, pos, c, s);
            const float* qh = q + (size_t)(head0+g)*Dn;
            float x1 = qh[t], x2 = qh[t+64];
            qf[g*Dn + t]      = (x1*c - x2*s) * sk_scale;
            qf[g*Dn + t + 64] = (x1*s + x2*c) * sk_scale;
        }
    }
    __syncthreads();

    int s    = tid >> 1;
    int half = tid & 1;
    int d0   = half * 64;
    const int4* kp = (const int4*)(k_cache +
        ((((size_t)b*Pn + p)*Sn + s)*HKV + hkv)*Dn + d0);

    // batch all 16 loads for MLP=16
    int4 kv[16];
    #pragma unroll
    for (int j = 0; j < 16; j++) kv[j] = kp[j];

    float a0=0.f, a1=0.f, a2=0.f, a3=0.f;
    int q4base = half * 16;
    #pragma unroll
    for (int j = 0; j < 16; j++) {
        float f0=(float)kv[j].x, f1=(float)kv[j].y,
              f2=(float)kv[j].z, f3=(float)kv[j].w;
        float4 q0 = qs4[0][q4base+j];
        float4 q1 = qs4[1][q4base+j];
        float4 q2 = qs4[2][q4base+j];
        float4 q3 = qs4[3][q4base+j];
        a0 += f0*q0.x + f1*q0.y + f2*q0.z + f3*q0.w;
        a1 += f0*q1.x + f1*q1.y + f2*q1.z + f3*q1.w;
        a2 += f0*q2.x + f1*q2.y + f2*q2.z + f3*q2.w;
        a3 += f0*q3.x + f1*q3.y + f2*q3.z + f3*q3.w;
    }

    // combine D-halves (lanes 2s, 2s+1)
    a0 += __shfl_xor_sync(0xffffffffu, a0, 1);
    a1 += __shfl_xor_sync(0xffffffffu, a1, 1);
    a2 += __shfl_xor_sync(0xffffffffu, a2, 1);
    a3 += __shfl_xor_sync(0xffffffffu, a3, 1);

    int pos_tok = p*Sn + s;
    bool valid = pos_tok < len;
    float sc[4];
    sc[0] = valid ? a0 : NEGV;
    sc[1] = valid ? a1 : NEGV;
    sc[2] = valid ? a2 : NEGV;
    sc[3] = valid ? a3 : NEGV;

    if (half == 0) {
        #pragma unroll
        for (int g = 0; g < Gn; g++)
            g_scores[(size_t)(head0+g)*Pn*Sn + p*Sn + s] = sc[g];
    }

    // per-page max per g
    __shared__ float wmax[4][Gn];
    int warp = tid >> 5, lane = tid & 31;
    #pragma unroll
    for (int g = 0; g < Gn; g++) {
        float v = sc[g];
        #pragma unroll
        for (int o = 16; o >= 1; o >>= 1)
            v = fmaxf(v, __shfl_xor_sync(0xffffffffu, v, o));
        if (lane == 0) wmax[warp][g] = v;
    }
    __syncthreads();
    if (tid < Gn) {
        float v = fmaxf(fmaxf(wmax[0][tid], wmax[1][tid]),
                        fmaxf(wmax[2][tid], wmax[3][tid]));
        g_stats[(head0+tid)*Pn + p] = v;
    }
}

// ---------------------------------------------------------------- kernel 2
// One WARP per head (4 heads/block, 32 blocks). Inline RoPE current score,
// register-resident top-15 (jax.lax.top_k semantics) + forced page 127.
__device__ __forceinline__ unsigned int fkey(float f) {
    unsigned int u = __float_as_uint(f);
    return u ^ ((u & 0x80000000u) ? 0xFFFFFFFFu : 0x80000000u);
}

__global__ void topk_kernel(const float* __restrict__ q,
                            const float* __restrict__ k,
                            const int*   __restrict__ timestep,
                            float* __restrict__ out_idx, int write_idx)
{
    int head = blockIdx.x * 4 + (threadIdx.x >> 5);
    int lane = threadIdx.x & 31;
    int b = head >> 5;
    int hkv = (head & (Hn-1)) >> 2;

    // current-token score with inline rope on q and k
    float pos = (float)(timestep[0] - 1);
    const float* qh = q + (size_t)head*Dn;
    const float* kh = k + (size_t)(b*HKV + hkv)*Dn;
    float prod = 0.f;
    #pragma unroll
    for (int j = 0; j < 2; j++) {
        int t = lane + j*32;
        float c, s; rope_cs(t, pos, c, s);
        float q1 = qh[t], q2 = qh[t+64];
        float k1 = kh[t], k2 = kh[t+64];
        prod += (q1*c - q2*s)*(k1*c - k2*s) + (q1*s + q2*c)*(k1*s + k2*c);
    }
    #pragma unroll
    for (int o = 16; o >= 1; o >>= 1)
        prod += __shfl_xor_sync(0xffffffffu, prod, o);
    float curv = prod * SM_SCALE;

    // register-resident top-15: lane owns indices lane, +32, +64, +96
    const float* st = g_stats + head*Pn;
    unsigned long long keys[4];
    #pragma unroll
    for (int j = 0; j < 4; j++) {
        int idx = lane + j*32;
        keys[j] = (idx < Pn-1)
            ? (((unsigned long long)fkey(st[idx]) << 32) | (unsigned int)(~idx))
            : 0ull;
    }

    int mysel = 0;
    int bidx0 = 0;
    #pragma unroll
    for (int it = 0; it < KP-1; it++) {
        unsigned long long best = keys[0];
        #pragma unroll
        for (int j = 1; j < 4; j++) best = (keys[j] > best) ? keys[j] : best;
        #pragma unroll
        for (int o = 16; o >= 1; o >>= 1) {
            unsigned long long u = __shfl_xor_sync(0xffffffffu, best, o);
            best = (u > best) ? u : best;
        }
        int bidx = (int)(~(unsigned int)(best & 0xFFFFFFFFull));
        if (lane == it) mysel = bidx;
        if (it == 0) bidx0 = bidx;
        #pragma unroll
        for (int j = 0; j < 4; j++) if (keys[j] == best) keys[j] = 0ull;
    }

    if (lane < KP-1) {
        g_sel[head*KP + lane] = mysel;
        if (write_idx) out_idx[head*KP + lane] = (float)mysel;
    }
    if (lane == KP-1) {
        g_sel[head*KP + lane] = Pn-1;
        if (write_idx) out_idx[head*KP + lane] = (float)(Pn-1);
    }
    if (lane == 0) {
        g_cur[head] = curv;
        float m = fmaxf(st[bidx0], st[Pn-1]);
        g_max[head] = fmaxf(m, curv);
    }
}

// ---------------------------------------------------------------- kernel 3
// One block per (head, selected page): 2048 blocks x 128 threads.
// Partial exp-weighted V sums; the last arriving block per head finalizes.
__global__ void __launch_bounds__(128, 5)
attn_kernel(const int*   __restrict__ v_cache,
            const float* __restrict__ v_cur,
            const float* __restrict__ kv_scale,
            float* __restrict__ out)
{
    __shared__ float  w[Sn];
    __shared__ float4 part[4][32];
    __shared__ int    s_last;

    int bid  = blockIdx.x;
    int head = bid >> 4;
    int kp   = bid & (KP-1);
    int tid  = threadIdx.x;
    int warp = tid >> 5, lane = tid & 31;
    int b = head >> 5;
    int hkv = (head & (Hn-1)) >> 2;

    int page = g_sel[head*KP + kp];
    float m  = g_max[head];

    if (tid < Sn)
        w[tid] = expf(g_scores[(size_t)head*Pn*Sn + page*Sn + tid] - m);
    __syncthreads();

    if (warp == 0) {
        float s = w[lane] + w[lane + 32];
        #pragma unroll
        for (int o = 16; o >= 1; o >>= 1)
            s += __shfl_xor_sync(0xffffffffu, s, o);
        if (lane == 0) g_pden[head*KP + kp] = s;
    }

    // V accumulation: warp handles tokens s == warp (mod 4); batch 16 loads
    const int4* vp = (const int4*)(v_cache +
        (((size_t)(b*Pn + page)*Sn)*HKV + hkv)*Dn) + lane;
    int4 vv[16];
    #pragma unroll
    for (int s2 = 0; s2 < 16; s2++)
        vv[s2] = vp[(size_t)(s2*4 + warp) * (HKV*Dn/4)];

    float a0=0.f, a1=0.f, a2=0.f, a3=0.f;
    #pragma unroll
    for (int s2 = 0; s2 < 16; s2++) {
        float ww = w[s2*4 + warp];
        a0 += ww*(float)vv[s2].x; a1 += ww*(float)vv[s2].y;
        a2 += ww*(float)vv[s2].z; a3 += ww*(float)vv[s2].w;
    }
    part[warp][lane] = make_float4(a0, a1, a2, a3);
    __syncthreads();

    {
        int lane2 = tid >> 2, comp = tid & 3;
        float acc = 0.f;
        #pragma unroll
        for (int g2 = 0; g2 < 4; g2++) {
            float4 pv = part[g2][lane2];
            acc += (comp==0) ? pv.x : (comp==1) ? pv.y : (comp==2) ? pv.z : pv.w;
        }
        g_part[((size_t)head*KP + kp)*Dn + tid] = acc;
    }

    // arrival counter: last block of this head finalizes (deterministic sum)
    __threadfence();
    __syncthreads();
    if (tid == 0) {
        int old = atomicAdd(&g_cnt[head], 1);
        s_last = (old == KP-1) ? 1 : 0;
        if (s_last) g_cnt[head] = 0;   // reset for next graph replay
    }
    __syncthreads();
    if (!s_last) return;
    __threadfence();

    float acc = 0.f;
    const float* pp = g_part + (size_t)head*KP*Dn + tid;
    #pragma unroll
    for (int j = 0; j < KP; j++) acc += pp[j*Dn];

    float ecur = expf(g_cur[head] - m);
    float den = ecur;
    const float* dp = g_pden + head*KP;
    #pragma unroll
    for (int j = 0; j < KP; j++) den += dp[j];

    float o = acc * kv_scale[1] + ecur * v_cur[(size_t)(b*HKV + hkv)*Dn + tid];
    out[(size_t)head*Dn + tid] = o / den;
}

// ---------------------------------------------------------------- launch
extern "C" void kernel_launch(void* const* d_in, const int* in_sizes, int n_in,
                              void* d_out, int out_size)
{
    const float* q        = (const float*)d_in[0];
    const float* k        = (const float*)d_in[1];
    const float* v        = (const float*)d_in[2];
    const float* kv_scale = (const float*)d_in[3];
    const int*   k_cache  = (const int*)  d_in[4];
    const int*   v_cache  = (const int*)  d_in[5];
    const int*   lengths  = (const int*)  d_in[6];
    const int*   timestep = (const int*)  d_in[7];
    float* out = (float*)d_out;

    int write_idx = (out_size >= Bn*Hn*Dn + Bn*Hn*KP) ? 1 : 0;

    score_kernel<<<dim3(Pn, Bn*HKV), 128>>>(q, k_cache, kv_scale, lengths, timestep);
    topk_kernel<<<Bn*Hn/4, 128>>>(q, k, timestep, out + Bn*Hn*Dn, write_idx);
    attn_kernel<<<Bn*Hn*KP, 128>>>(v_cache, v, kv_scale, out);
}

// round 4
// speedup vs baseline: 1.2983x; 1.2983x over previous
#include <cuda_runtime.h>
#include <math.h>
#include <float.h>

#define Bn   4
#define Hn   32
#define HKV  8
#define Gn   4
#define Dn   128
#define Pn   128
#define Sn   64
#define KP   16
#define NEGV (-1000000000.0f)
#define SM_SCALE 0.08838834764831845f

// Scratch (allocation-free rule: __device__ globals)
__device__ float g_scores[Bn*Hn*Pn*Sn];   // 4 MB masked score matrix
__device__ float g_stats [Bn*Hn*Pn];      // per-page max
__device__ int   g_sel   [Bn*Hn*KP];
__device__ float g_cur   [Bn*Hn];         // current-token score
__device__ float g_max   [Bn*Hn];         // softmax max per head
__device__ float g_part  [Bn*Hn*KP*Dn];   // per-(head,page) partial sum(exp*V)
__device__ float g_pden  [Bn*Hn*KP];      // per-(head,page) partial denom
__device__ int   g_cnt   [Bn*Hn];         // arrival counters (zero-init)

__device__ __forceinline__ void rope_cs(int t, float pos, float& c, float& s) {
    float inv = 1.0f / powf(10000.0f, (float)t * (2.0f / (float)Dn));
    float ang = pos * inv;
    c = cosf(ang); s = sinf(ang);
}

// ---------------------------------------------------------------- kernel 1
// One block per (page, b*HKV): 256 threads, 8 warps x 8 tokens.
// Lane owns dims [4*lane, 4*lane+4): every LDG.128 reads one token's
// contiguous 512B (4 lines). q in registers (RoPE'd + pre-scaled).
// Butterfly transpose-reduce: 32 dots (4 heads x 8 tokens) per warp.
__global__ void __launch_bounds__(256, 3)
score_kernel(const float* __restrict__ q,
             const int*   __restrict__ k_cache,
             const float* __restrict__ kv_scale,
             const int*   __restrict__ lengths,
             const int*   __restrict__ timestep)
{
    int p   = blockIdx.x;
    int bh  = blockIdx.y;            // b*HKV + hkv
    int b   = bh >> 3, hkv = bh & 7;
    int tid = threadIdx.x;
    int w   = tid >> 5, lane = tid & 31;
    int len = max(lengths[b], 1);
    int head0 = b*Hn + hkv*Gn;

    if (p*Sn >= len) {
        // fully masked page. Only page Pn-1 can ever be selected while masked.
        if (p == Pn-1 && tid < Sn) {
            #pragma unroll
            for (int g = 0; g < Gn; g++)
                g_scores[(size_t)(head0+g)*Pn*Sn + p*Sn + tid] = NEGV;
        }
        if (tid < Gn) g_stats[(head0+tid)*Pn + p] = NEGV;
        return;
    }

    // --- q into registers: lane owns dims 4*lane..4*lane+3, all 4 heads.
    // RoPE pairs dim d (<64) with d+64: exchange with lane^16.
    float pos = (float)(timestep[0] - 1);
    float sk  = kv_scale[0] * SM_SCALE;
    bool low  = lane < 16;
    int hb    = low ? 4*lane : 4*lane - 64;   // freq index base
    float cc[4], ss[4];
    #pragma unroll
    for (int i = 0; i < 4; i++) rope_cs(hb + i, pos, cc[i], ss[i]);

    float4 qr[Gn];
    #pragma unroll
    for (int g = 0; g < Gn; g++) {
        float4 own = *(const float4*)(q + (size_t)(head0+g)*Dn + 4*lane);
        float po[4], ow[4] = {own.x, own.y, own.z, own.w};
        #pragma unroll
        for (int i = 0; i < 4; i++)
            po[i] = __shfl_xor_sync(0xffffffffu, ow[i], 16);
        float r[4];
        #pragma unroll
        for (int i = 0; i < 4; i++) {
            // low: x1=own, x2=partner -> x1*c - x2*s
            // high: x1=partner, x2=own -> x1*s + x2*c
            r[i] = low ? (ow[i]*cc[i] - po[i]*ss[i])
                       : (po[i]*ss[i] + ow[i]*cc[i]);
            r[i] *= sk;
        }
        qr[g] = make_float4(r[0], r[1], r[2], r[3]);
    }

    // --- main loop: warp w handles tokens w*8 .. w*8+7
    const int4* kbase = (const int4*)(k_cache +
        ((((size_t)b*Pn + p)*Sn + w*8)*HKV + hkv)*Dn) + lane;

    float vals[32];
    #pragma unroll
    for (int i = 0; i < 32; i++) vals[i] = 0.f;

    #pragma unroll
    for (int t = 0; t < 8; t++) {
        int4 kv = kbase[t * (HKV*Dn/4)];
        float f0=(float)kv.x, f1=(float)kv.y, f2=(float)kv.z, f3=(float)kv.w;
        #pragma unroll
        for (int g = 0; g < Gn; g++)
            vals[g*8+t] += f0*qr[g].x + f1*qr[g].y + f2*qr[g].z + f3*qr[g].w;
    }

    // --- butterfly transpose-reduce: lane l ends with total of vals[l]
    #pragma unroll
    for (int o = 16; o >= 1; o >>= 1) {
        #pragma unroll
        for (int a = 0; a < o; a++) {
            float lo = vals[a], hi = vals[a+o];
            float send = (lane & o) ? lo : hi;
            float recv = __shfl_xor_sync(0xffffffffu, send, o);
            vals[a] = ((lane & o) ? hi : lo) + recv;
        }
    }

    // lane -> (g = lane>>3, tl = lane&7), token = w*8 + tl
    int g  = lane >> 3, tl = lane & 7;
    int t  = w*8 + tl;
    float sc = (p*Sn + t < len) ? vals[0] : NEGV;
    g_scores[(size_t)(head0+g)*Pn*Sn + p*Sn + t] = sc;

    // page max per g: reduce over tl (groups of 8), then over warps
    __shared__ float smax[8][Gn];
    float m = sc;
    #pragma unroll
    for (int o = 4; o >= 1; o >>= 1)
        m = fmaxf(m, __shfl_xor_sync(0xffffffffu, m, o));
    if (tl == 0) smax[w][g] = m;
    __syncthreads();
    if (tid < 32) {
        // tid = g2*8 + w2
        float v = smax[tid & 7][tid >> 3];
        #pragma unroll
        for (int o = 4; o >= 1; o >>= 1)
            v = fmaxf(v, __shfl_xor_sync(0xffffffffu, v, o));
        if ((tid & 7) == 0)
            g_stats[(head0 + (tid >> 3))*Pn + p] = v;
    }
}

// ---------------------------------------------------------------- kernel 2
// One WARP per head (4 heads/block, 32 blocks). Inline RoPE current score,
// register-resident top-15 (jax.lax.top_k semantics) + forced page 127.
__device__ __forceinline__ unsigned int fkey(float f) {
    unsigned int u = __float_as_uint(f);
    return u ^ ((u & 0x80000000u) ? 0xFFFFFFFFu : 0x80000000u);
}

__global__ void topk_kernel(const float* __restrict__ q,
                            const float* __restrict__ k,
                            const int*   __restrict__ timestep,
                            float* __restrict__ out_idx, int write_idx)
{
    int head = blockIdx.x * 4 + (threadIdx.x >> 5);
    int lane = threadIdx.x & 31;
    int b = head >> 5;
    int hkv = (head & (Hn-1)) >> 2;

    // current-token score with inline rope on q and k
    float pos = (float)(timestep[0] - 1);
    const float* qh = q + (size_t)head*Dn;
    const float* kh = k + (size_t)(b*HKV + hkv)*Dn;
    float prod = 0.f;
    #pragma unroll
    for (int j = 0; j < 2; j++) {
        int t = lane + j*32;
        float c, s; rope_cs(t, pos, c, s);
        float q1 = qh[t], q2 = qh[t+64];
        float k1 = kh[t], k2 = kh[t+64];
        prod += (q1*c - q2*s)*(k1*c - k2*s) + (q1*s + q2*c)*(k1*s + k2*c);
    }
    #pragma unroll
    for (int o = 16; o >= 1; o >>= 1)
        prod += __shfl_xor_sync(0xffffffffu, prod, o);
    float curv = prod * SM_SCALE;

    // register-resident top-15: lane owns indices lane, +32, +64, +96
    const float* st = g_stats + head*Pn;
    unsigned long long keys[4];
    #pragma unroll
    for (int j = 0; j < 4; j++) {
        int idx = lane + j*32;
        keys[j] = (idx < Pn-1)
            ? (((unsigned long long)fkey(st[idx]) << 32) | (unsigned int)(~idx))
            : 0ull;
    }

    int mysel = 0;
    int bidx0 = 0;
    #pragma unroll
    for (int it = 0; it < KP-1; it++) {
        unsigned long long best = keys[0];
        #pragma unroll
        for (int j = 1; j < 4; j++) best = (keys[j] > best) ? keys[j] : best;
        #pragma unroll
        for (int o = 16; o >= 1; o >>= 1) {
            unsigned long long u = __shfl_xor_sync(0xffffffffu, best, o);
            best = (u > best) ? u : best;
        }
        int bidx = (int)(~(unsigned int)(best & 0xFFFFFFFFull));
        if (lane == it) mysel = bidx;
        if (it == 0) bidx0 = bidx;
        #pragma unroll
        for (int j = 0; j < 4; j++) if (keys[j] == best) keys[j] = 0ull;
    }

    if (lane < KP-1) {
        g_sel[head*KP + lane] = mysel;
        if (write_idx) out_idx[head*KP + lane] = (float)mysel;
    }
    if (lane == KP-1) {
        g_sel[head*KP + lane] = Pn-1;
        if (write_idx) out_idx[head*KP + lane] = (float)(Pn-1);
    }
    if (lane == 0) {
        g_cur[head] = curv;
        float m = fmaxf(st[bidx0], st[Pn-1]);
        g_max[head] = fmaxf(m, curv);
    }
}

// ---------------------------------------------------------------- kernel 3
// One block per (head, selected page): 2048 blocks x 128 threads.
// Partial exp-weighted V sums; the last arriving block per head finalizes.
__global__ void __launch_bounds__(128, 5)
attn_kernel(const int*   __restrict__ v_cache,
            const float* __restrict__ v_cur,
            const float* __restrict__ kv_scale,
            float* __restrict__ out)
{
    __shared__ float  w[Sn];
    __shared__ float4 part[4][32];
    __shared__ int    s_last;

    int bid  = blockIdx.x;
    int head = bid >> 4;
    int kp   = bid & (KP-1);
    int tid  = threadIdx.x;
    int warp = tid >> 5, lane = tid & 31;
    int b = head >> 5;
    int hkv = (head & (Hn-1)) >> 2;

    int page = g_sel[head*KP + kp];
    float m  = g_max[head];

    if (tid < Sn)
        w[tid] = expf(g_scores[(size_t)head*Pn*Sn + page*Sn + tid] - m);
    __syncthreads();

    if (warp == 0) {
        float s = w[lane] + w[lane + 32];
        #pragma unroll
        for (int o = 16; o >= 1; o >>= 1)
            s += __shfl_xor_sync(0xffffffffu, s, o);
        if (lane == 0) g_pden[head*KP + kp] = s;
    }

    // V accumulation: warp handles tokens s == warp (mod 4); batch 16 loads
    const int4* vp = (const int4*)(v_cache +
        (((size_t)(b*Pn + page)*Sn)*HKV + hkv)*Dn) + lane;
    int4 vv[16];
    #pragma unroll
    for (int s2 = 0; s2 < 16; s2++)
        vv[s2] = vp[(size_t)(s2*4 + warp) * (HKV*Dn/4)];

    float a0=0.f, a1=0.f, a2=0.f, a3=0.f;
    #pragma unroll
    for (int s2 = 0; s2 < 16; s2++) {
        float ww = w[s2*4 + warp];
        a0 += ww*(float)vv[s2].x; a1 += ww*(float)vv[s2].y;
        a2 += ww*(float)vv[s2].z; a3 += ww*(float)vv[s2].w;
    }
    part[warp][lane] = make_float4(a0, a1, a2, a3);
    __syncthreads();

    {
        int lane2 = tid >> 2, comp = tid & 3;
        float acc = 0.f;
        #pragma unroll
        for (int g2 = 0; g2 < 4; g2++) {
            float4 pv = part[g2][lane2];
            acc += (comp==0) ? pv.x : (comp==1) ? pv.y : (comp==2) ? pv.z : pv.w;
        }
        g_part[((size_t)head*KP + kp)*Dn + tid] = acc;
    }

    // arrival counter: last block of this head finalizes (deterministic sum)
    __threadfence();
    __syncthreads();
    if (tid == 0) {
        int old = atomicAdd(&g_cnt[head], 1);
        s_last = (old == KP-1) ? 1 : 0;
        if (s_last) g_cnt[head] = 0;   // reset for next graph replay
    }
    __syncthreads();
    if (!s_last) return;
    __threadfence();

    float acc = 0.f;
    const float* pp = g_part + (size_t)head*KP*Dn + tid;
    #pragma unroll
    for (int j = 0; j < KP; j++) acc += pp[j*Dn];

    float ecur = expf(g_cur[head] - m);
    float den = ecur;
    const float* dp = g_pden + head*KP;
    #pragma unroll
    for (int j = 0; j < KP; j++) den += dp[j];

    float o = acc * kv_scale[1] + ecur * v_cur[(size_t)(b*HKV + hkv)*Dn + tid];
    out[(size_t)head*Dn + tid] = o / den;
}

// ---------------------------------------------------------------- launch
extern "C" void kernel_launch(void* const* d_in, const int* in_sizes, int n_in,
                              void* d_out, int out_size)
{
    const float* q        = (const float*)d_in[0];
    const float* k        = (const float*)d_in[1];
    const float* v        = (const float*)d_in[2];
    const float* kv_scale = (const float*)d_in[3];
    const int*   k_cache  = (const int*)  d_in[4];
    const int*   v_cache  = (const int*)  d_in[5];
    const int*   lengths  = (const int*)  d_in[6];
    const int*   timestep = (const int*)  d_in[7];
    float* out = (float*)d_out;

    int write_idx = (out_size >= Bn*Hn*Dn + Bn*Hn*KP) ? 1 : 0;

    score_kernel<<<dim3(Pn, Bn*HKV), 256>>>(q, k_cache, kv_scale, lengths, timestep);
    topk_kernel<<<Bn*Hn/4, 128>>>(q, k, timestep, out + Bn*Hn*Dn, write_idx);
    attn_kernel<<<Bn*Hn*KP, 128>>>(v_cache, v, kv_scale, out);
}

// round 5
// speedup vs baseline: 1.5208x; 1.1714x over previous
#include <cuda_runtime.h>
#include <math.h>
#include <float.h>

#define Bn   4
#define Hn   32
#define HKV  8
#define Gn   4
#define Dn   128
#define Pn   128
#define Sn   64
#define KP   16
#define NEGV (-1000000000.0f)
#define SM_SCALE 0.08838834764831845f

// Scratch (allocation-free rule: __device__ globals)
__device__ float g_qr    [Bn*Hn*Dn];      // roped q (unscaled)
__device__ float g_kr    [Bn*HKV*Dn];     // roped current k
__device__ float g_scores[Bn*Hn*Pn*Sn];   // 4 MB masked score matrix
__device__ float g_stats [Bn*Hn*Pn];      // per-page max
__device__ int   g_sel   [Bn*Hn*KP];
__device__ float g_cur   [Bn*Hn];         // current-token score
__device__ float g_max   [Bn*Hn];         // softmax max per head
__device__ float g_part  [Bn*Hn*KP*Dn];   // per-(head,page) partial sum(exp*V)
__device__ float g_pden  [Bn*Hn*KP];      // per-(head,page) partial denom
__device__ int   g_cnt   [Bn*Hn];         // arrival counters (zero-init)

__device__ __forceinline__ void rope_cs(int t, float pos, float& c, float& s) {
    float inv = 1.0f / powf(10000.0f, (float)t * (2.0f / (float)Dn));
    float ang = pos * inv;
    c = cosf(ang); s = sinf(ang);
}

// ---------------------------------------------------------------- kernel 0
// RoPE (neox) for q (B*H heads) and current k (B*HKV heads). 64 threads/blk.
__global__ void prep_kernel(const float* __restrict__ q,
                            const float* __restrict__ k,
                            const int*   __restrict__ timestep)
{
    int i = blockIdx.x;          // 0..159
    int t = threadIdx.x;         // 0..63
    float pos = (float)(timestep[0] - 1);
    float c, s; rope_cs(t, pos, c, s);

    const float* src;
    float* dst;
    if (i < Bn*Hn) { src = q + (size_t)i*Dn;          dst = g_qr + (size_t)i*Dn; }
    else           { src = k + (size_t)(i-Bn*Hn)*Dn;  dst = g_kr + (size_t)(i-Bn*Hn)*Dn; }

    float x1 = src[t], x2 = src[t+64];
    dst[t]    = x1*c - x2*s;
    dst[t+64] = x1*s + x2*c;
}

// ---------------------------------------------------------------- kernel 1
// One block per (page, b*HKV): 256 threads, 8 warps x 8 tokens.
// Lane owns dims [4*lane, 4*lane+4); q pre-roped in registers.
// Two 4-token chunks; butterfly transpose-reduce of 16 vals over 32 lanes.
__global__ void __launch_bounds__(256, 4)
score_kernel(const int*   __restrict__ k_cache,
             const float* __restrict__ kv_scale,
             const int*   __restrict__ lengths)
{
    int p   = blockIdx.x;
    int bh  = blockIdx.y;            // b*HKV + hkv
    int b   = bh >> 3, hkv = bh & 7;
    int tid = threadIdx.x;
    int w   = tid >> 5, lane = tid & 31;
    int len = max(lengths[b], 1);
    int head0 = b*Hn + hkv*Gn;

    if (p*Sn >= len) {
        // fully masked page. Only page Pn-1 can ever be selected while masked.
        if (p == Pn-1 && tid < Sn) {
            #pragma unroll
            for (int g = 0; g < Gn; g++)
                g_scores[(size_t)(head0+g)*Pn*Sn + p*Sn + tid] = NEGV;
        }
        if (tid < Gn) g_stats[(head0+tid)*Pn + p] = NEGV;
        return;
    }

    // q: lane owns dims 4*lane..4*lane+3, all 4 heads (pre-roped, unscaled)
    float4 qr[Gn];
    #pragma unroll
    for (int g = 0; g < Gn; g++)
        qr[g] = *(const float4*)(g_qr + (size_t)(head0+g)*Dn + 4*lane);

    float sks = kv_scale[0] * SM_SCALE;

    const int4* kbase = (const int4*)(k_cache +
        ((((size_t)b*Pn + p)*Sn + w*8)*HKV + hkv)*Dn) + lane;

    // lane -> (g, t) after butterfly: g = (lane>>3)&3, t = (lane>>1)&3
    int g  = (lane >> 3) & 3;
    int tt = (lane >> 1) & 3;

    float pmax = NEGV;
    #pragma unroll
    for (int c = 0; c < 2; c++) {
        int4 kv[4];
        #pragma unroll
        for (int t = 0; t < 4; t++)
            kv[t] = kbase[(size_t)(c*4 + t) * (HKV*Dn/4)];

        float vals[16];
        #pragma unroll
        for (int i = 0; i < 16; i++) vals[i] = 0.f;

        #pragma unroll
        for (int t = 0; t < 4; t++) {
            float f0=(float)kv[t].x, f1=(float)kv[t].y,
                  f2=(float)kv[t].z, f3=(float)kv[t].w;
            #pragma unroll
            for (int gg = 0; gg < Gn; gg++)
                vals[gg*4+t] += f0*qr[gg].x + f1*qr[gg].y
                              + f2*qr[gg].z + f3*qr[gg].w;
        }

        // butterfly: stages (o=16,d=8) (8,4) (4,2) (2,1); then fold lane bit 0
        #pragma unroll
        for (int st = 0; st < 4; st++) {
            int o = 16 >> st, d = 8 >> st;
            #pragma unroll
            for (int a = 0; a < 8; a++) {
                if (a >= d) break;
                float lo = vals[a], hi = vals[a+d];
                float send = (lane & o) ? lo : hi;
                float recv = __shfl_xor_sync(0xffffffffu, send, o);
                vals[a] = ((lane & o) ? hi : lo) + recv;
            }
        }
        float v = vals[0] + __shfl_xor_sync(0xffffffffu, vals[0], 1);

        int tok = w*8 + c*4 + tt;
        bool valid = p*Sn + tok < len;
        float sc = valid ? v*sks : NEGV;
        if (!(lane & 1))
            g_scores[(size_t)(head0+g)*Pn*Sn + p*Sn + tok] = sc;
        pmax = fmaxf(pmax, sc);
    }

    // per-g page max: reduce over lane bits 4,2 (bit 1 already duplicated)
    pmax = fmaxf(pmax, __shfl_xor_sync(0xffffffffu, pmax, 4));
    pmax = fmaxf(pmax, __shfl_xor_sync(0xffffffffu, pmax, 2));

    __shared__ float smax[8][Gn];
    if ((lane & 7) == 0) smax[w][g] = pmax;
    __syncthreads();
    if (tid < 32) {
        // tid = g2*8 + w2
        float v = smax[tid & 7][tid >> 3];
        #pragma unroll
        for (int o = 4; o >= 1; o >>= 1)
            v = fmaxf(v, __shfl_xor_sync(0xffffffffu, v, o));
        if ((tid & 7) == 0)
            g_stats[(head0 + (tid >> 3))*Pn + p] = v;
    }
}

// ---------------------------------------------------------------- kernel 2
// One WARP per head (4 heads/block, 32 blocks). Current score from pre-roped
// q/k; register-resident top-15 (jax.lax.top_k semantics) + forced page 127.
__device__ __forceinline__ unsigned int fkey(float f) {
    unsigned int u = __float_as_uint(f);
    return u ^ ((u & 0x80000000u) ? 0xFFFFFFFFu : 0x80000000u);
}

__global__ void topk_kernel(float* __restrict__ out_idx, int write_idx)
{
    int head = blockIdx.x * 4 + (threadIdx.x >> 5);
    int lane = threadIdx.x & 31;
    int b = head >> 5;
    int hkv = (head & (Hn-1)) >> 2;

    // current-token score from pre-roped vectors
    float4 qa = *(const float4*)(g_qr + (size_t)head*Dn + 4*lane);
    float4 ka = *(const float4*)(g_kr + (size_t)(b*HKV + hkv)*Dn + 4*lane);
    float prod = qa.x*ka.x + qa.y*ka.y + qa.z*ka.z + qa.w*ka.w;
    #pragma unroll
    for (int o = 16; o >= 1; o >>= 1)
        prod += __shfl_xor_sync(0xffffffffu, prod, o);
    float curv = prod * SM_SCALE;

    // register-resident top-15: lane owns indices lane, +32, +64, +96
    const float* st = g_stats + head*Pn;
    unsigned long long keys[4];
    #pragma unroll
    for (int j = 0; j < 4; j++) {
        int idx = lane + j*32;
        keys[j] = (idx < Pn-1)
            ? (((unsigned long long)fkey(st[idx]) << 32) | (unsigned int)(~idx))
            : 0ull;
    }

    int mysel = 0;
    int bidx0 = 0;
    #pragma unroll
    for (int it = 0; it < KP-1; it++) {
        unsigned long long best = keys[0];
        #pragma unroll
        for (int j = 1; j < 4; j++) best = (keys[j] > best) ? keys[j] : best;
        #pragma unroll
        for (int o = 16; o >= 1; o >>= 1) {
            unsigned long long u = __shfl_xor_sync(0xffffffffu, best, o);
            best = (u > best) ? u : best;
        }
        int bidx = (int)(~(unsigned int)(best & 0xFFFFFFFFull));
        if (lane == it) mysel = bidx;
        if (it == 0) bidx0 = bidx;
        #pragma unroll
        for (int j = 0; j < 4; j++) if (keys[j] == best) keys[j] = 0ull;
    }

    if (lane < KP-1) {
        g_sel[head*KP + lane] = mysel;
        if (write_idx) out_idx[head*KP + lane] = (float)mysel;
    }
    if (lane == KP-1) {
        g_sel[head*KP + lane] = Pn-1;
        if (write_idx) out_idx[head*KP + lane] = (float)(Pn-1);
    }
    if (lane == 0) {
        g_cur[head] = curv;
        float m = fmaxf(st[bidx0], st[Pn-1]);
        g_max[head] = fmaxf(m, curv);
    }
}

// ---------------------------------------------------------------- kernel 3
// One block per (head, selected page): 2048 blocks x 128 threads.
// Partial exp-weighted V sums; the last arriving block per head finalizes.
__global__ void __launch_bounds__(128, 5)
attn_kernel(const int*   __restrict__ v_cache,
            const float* __restrict__ v_cur,
            const float* __restrict__ kv_scale,
            float* __restrict__ out)
{
    __shared__ float  w[Sn];
    __shared__ float4 part[4][32];
    __shared__ int    s_last;

    int bid  = blockIdx.x;
    int head = bid >> 4;
    int kp   = bid & (KP-1);
    int tid  = threadIdx.x;
    int warp = tid >> 5, lane = tid & 31;
    int b = head >> 5;
    int hkv = (head & (Hn-1)) >> 2;

    int page = g_sel[head*KP + kp];
    float m  = g_max[head];

    if (tid < Sn)
        w[tid] = expf(g_scores[(size_t)head*Pn*Sn + page*Sn + tid] - m);
    __syncthreads();

    if (warp == 0) {
        float s = w[lane] + w[lane + 32];
        #pragma unroll
        for (int o = 16; o >= 1; o >>= 1)
            s += __shfl_xor_sync(0xffffffffu, s, o);
        if (lane == 0) g_pden[head*KP + kp] = s;
    }

    // V accumulation: warp handles tokens s == warp (mod 4); batch 16 loads
    const int4* vp = (const int4*)(v_cache +
        (((size_t)(b*Pn + page)*Sn)*HKV + hkv)*Dn) + lane;
    int4 vv[16];
    #pragma unroll
    for (int s2 = 0; s2 < 16; s2++)
        vv[s2] = vp[(size_t)(s2*4 + warp) * (HKV*Dn/4)];

    float a0=0.f, a1=0.f, a2=0.f, a3=0.f;
    #pragma unroll
    for (int s2 = 0; s2 < 16; s2++) {
        float ww = w[s2*4 + warp];
        a0 += ww*(float)vv[s2].x; a1 += ww*(float)vv[s2].y;
        a2 += ww*(float)vv[s2].z; a3 += ww*(float)vv[s2].w;
    }
    part[warp][lane] = make_float4(a0, a1, a2, a3);
    __syncthreads();

    {
        int lane2 = tid >> 2, comp = tid & 3;
        float acc = 0.f;
        #pragma unroll
        for (int g2 = 0; g2 < 4; g2++) {
            float4 pv = part[g2][lane2];
            acc += (comp==0) ? pv.x : (comp==1) ? pv.y : (comp==2) ? pv.z : pv.w;
        }
        g_part[((size_t)head*KP + kp)*Dn + tid] = acc;
    }

    // arrival counter: last block of this head finalizes (deterministic sum)
    __threadfence();
    __syncthreads();
    if (tid == 0) {
        int old = atomicAdd(&g_cnt[head], 1);
        s_last = (old == KP-1) ? 1 : 0;
        if (s_last) g_cnt[head] = 0;   // reset for next graph replay
    }
    __syncthreads();
    if (!s_last) return;
    __threadfence();

    float acc = 0.f;
    const float* pp = g_part + (size_t)head*KP*Dn + tid;
    #pragma unroll
    for (int j = 0; j < KP; j++) acc += pp[j*Dn];

    float ecur = expf(g_cur[head] - m);
    float den = ecur;
    const float* dp = g_pden + head*KP;
    #pragma unroll
    for (int j = 0; j < KP; j++) den += dp[j];

    float o = acc * kv_scale[1] + ecur * v_cur[(size_t)(b*HKV + hkv)*Dn + tid];
    out[(size_t)head*Dn + tid] = o / den;
}

// ---------------------------------------------------------------- launch
extern "C" void kernel_launch(void* const* d_in, const int* in_sizes, int n_in,
                              void* d_out, int out_size)
{
    const float* q        = (const float*)d_in[0];
    const float* k        = (const float*)d_in[1];
    const float* v        = (const float*)d_in[2];
    const float* kv_scale = (const float*)d_in[3];
    const int*   k_cache  = (const int*)  d_in[4];
    const int*   v_cache  = (const int*)  d_in[5];
    const int*   lengths  = (const int*)  d_in[6];
    const int*   timestep = (const int*)  d_in[7];
    float* out = (float*)d_out;

    int write_idx = (out_size >= Bn*Hn*Dn + Bn*Hn*KP) ? 1 : 0;

    prep_kernel<<<Bn*Hn + Bn*HKV, 64>>>(q, k, timestep);
    score_kernel<<<dim3(Pn, Bn*HKV), 256>>>(k_cache, kv_scale, lengths);
    topk_kernel<<<Bn*Hn/4, 128>>>(out + Bn*Hn*Dn, write_idx);
    attn_kernel<<<Bn*Hn*KP, 128>>>(v_cache, v, kv_scale, out);
}